// round 2
// baseline (speedup 1.0000x reference)
#include <cuda_runtime.h>
#include <cuda_bf16.h>
#include <cstdint>

#define BATCH 16
#define NTOK  4096
#define CDIM  512
#define JDIM  64
#define ROWS  (BATCH*NTOK)   // 65536

// ---------- scratch (device globals; no runtime allocation) ----------
__device__ __nv_bfloat16 g_Wbf[JDIM*CDIM];   // fused w1@m0, stored [j][c] (col-major B for mma)
__device__ float         g_blog[JDIM];       // b1@m0
__device__ __nv_bfloat16 g_Mbf[CDIM*JDIM];   // fused m1@w2, stored [c][j] (col-major B for mma)
__device__ float         g_bns[CDIM], g_bnt[CDIM];
__device__ float         g_logits[ROWS*JDIM];            // 16 MiB
__device__ float         g_pmax[BATCH*8*JDIM], g_psum[BATCH*8*JDIM];
__device__ float         g_rmax[BATCH*JDIM],  g_rinv[BATCH*JDIM];

// ---------- helpers ----------
__device__ __forceinline__ uint32_t packbf(float x, float y) {
    __nv_bfloat162 h = __floats2bfloat162_rn(x, y);
    return *reinterpret_cast<uint32_t*>(&h);
}

__device__ __forceinline__ void mma16816(float* c, const uint32_t* a, const uint32_t* b) {
    asm volatile(
        "mma.sync.aligned.m16n8k16.row.col.f32.bf16.bf16.f32 "
        "{%0,%1,%2,%3},{%4,%5,%6,%7},{%8,%9},{%0,%1,%2,%3};"
        : "+f"(c[0]), "+f"(c[1]), "+f"(c[2]), "+f"(c[3])
        : "r"(a[0]), "r"(a[1]), "r"(a[2]), "r"(a[3]), "r"(b[0]), "r"(b[1]));
}

// ---------- K0: fold weights ----------
// W[c][j] = sum_q w1[c][q]*m0[q][j]     -> g_Wbf[j*512+c]  (bf16)
// M[j][c] = sum_q m1[j][q]*w2[q][c]     -> g_Mbf[c*64+j]   (bf16)
// bn scale/shift; blog[j] = sum_q b1[q]*m0[q][j]
__global__ void k_fuse(const float* __restrict__ w1, const float* __restrict__ b1,
                       const float* __restrict__ m0, const float* __restrict__ m1,
                       const float* __restrict__ w2, const float* __restrict__ gamma,
                       const float* __restrict__ beta, const float* __restrict__ bmean,
                       const float* __restrict__ bvar) {
    int idx = blockIdx.x * blockDim.x + threadIdx.x;
    if (idx < 32768) {
        int j = idx & 63, c = idx >> 6;
        float acc = 0.f;
        #pragma unroll 8
        for (int q = 0; q < CDIM; q++) acc += w1[c*CDIM + q] * m0[q*JDIM + j];
        g_Wbf[j*CDIM + c] = __float2bfloat16_rn(acc);
    } else if (idx < 65536) {
        int i = idx - 32768;
        int c = i & 511, j = i >> 9;
        float acc = 0.f;
        #pragma unroll 8
        for (int q = 0; q < CDIM; q++) acc += m1[j*CDIM + q] * w2[q*CDIM + c];
        g_Mbf[c*JDIM + j] = __float2bfloat16_rn(acc);
    } else if (idx < 65536 + CDIM) {
        int c = idx - 65536;
        float s = gamma[c] * rsqrtf(bvar[c] + 1e-3f);
        g_bns[c] = s;
        g_bnt[c] = beta[c] - bmean[c] * s;
    } else if (idx < 65536 + CDIM + JDIM) {
        int j = idx - 65536 - CDIM;
        float acc = 0.f;
        for (int q = 0; q < CDIM; q++) acc += b1[q] * m0[q*JDIM + j];
        g_blog[j] = acc;
    }
}

// ---------- K1: logits = inputs @ W + blog ----------
// M=65536, N=64, K=512. CTA=256 thr (8 warps), CTA tile 256 rows; warp tile 32x64.
// A frags loaded straight from global fp32 (32B-sector exact), W held in smem
// (two 256-wide K halves to stay under 48KB static smem).
__global__ __launch_bounds__(256) void k_logits(const float* __restrict__ in) {
    __shared__ __align__(16) __nv_bfloat16 sW[JDIM * 264]; // [j][k_half], stride 264 bf16 (pad)
    __shared__ float sblog[JDIM];
    int tid = threadIdx.x;
    if (tid < JDIM) sblog[tid] = g_blog[tid];

    uint32_t* sw32 = reinterpret_cast<uint32_t*>(sW);
    const uint32_t* gw = reinterpret_cast<const uint32_t*>(g_Wbf); // 256 words/row

    int warp = tid >> 5, lane = tid & 31;
    int qr = lane >> 2, qc = lane & 3;
    int rowbase = blockIdx.x * 256 + warp * 32;

    float acc[2][8][4];

    for (int kh = 0; kh < 2; kh++) {
        __syncthreads();
        for (int i = tid; i < JDIM * 128; i += 256) {
            int j = i >> 7, w = i & 127;
            sw32[j*132 + w] = gw[j*256 + kh*128 + w];
        }
        __syncthreads();

        if (kh == 0) {
            #pragma unroll
            for (int nt = 0; nt < 8; nt++) {
                float b0 = sblog[nt*8 + qc*2], b1v = sblog[nt*8 + qc*2 + 1];
                #pragma unroll
                for (int s = 0; s < 2; s++) {
                    acc[s][nt][0] = b0; acc[s][nt][1] = b1v;
                    acc[s][nt][2] = b0; acc[s][nt][3] = b1v;
                }
            }
        }

        const float* abase = in + (size_t)(rowbase + qr) * CDIM + qc*2 + kh*256;
        #pragma unroll 2
        for (int kk = 0; kk < 256; kk += 16) {
            uint32_t a[2][4];
            #pragma unroll
            for (int s = 0; s < 2; s++) {
                const float* p = abase + s*16*CDIM + kk;
                float2 v0 = *reinterpret_cast<const float2*>(p);
                float2 v1 = *reinterpret_cast<const float2*>(p + 8*CDIM);
                float2 v2 = *reinterpret_cast<const float2*>(p + 8);
                float2 v3 = *reinterpret_cast<const float2*>(p + 8*CDIM + 8);
                a[s][0] = packbf(v0.x, v0.y);
                a[s][1] = packbf(v1.x, v1.y);
                a[s][2] = packbf(v2.x, v2.y);
                a[s][3] = packbf(v3.x, v3.y);
            }
            int bofs = (kk + qc*2) >> 1;
            #pragma unroll
            for (int nt = 0; nt < 8; nt++) {
                int n = nt*8 + qr;
                uint32_t b[2];
                b[0] = sw32[n*132 + bofs];
                b[1] = sw32[n*132 + bofs + 4];
                mma16816(acc[0][nt], a[0], b);
                mma16816(acc[1][nt], a[1], b);
            }
        }
    }

    #pragma unroll
    for (int s = 0; s < 2; s++)
        #pragma unroll
        for (int nt = 0; nt < 8; nt++) {
            int row = rowbase + s*16 + qr;
            int col = nt*8 + qc*2;
            float2 lo = make_float2(acc[s][nt][0], acc[s][nt][1]);
            float2 hi = make_float2(acc[s][nt][2], acc[s][nt][3]);
            *reinterpret_cast<float2*>(&g_logits[(size_t)row*JDIM + col]) = lo;
            *reinterpret_cast<float2*>(&g_logits[(size_t)(row + 8)*JDIM + col]) = hi;
        }
}

// ---------- K2a: per-(b, chunk, j) max and sumexp over 512 tokens ----------
__global__ void k_stats1() { // grid (16, 8), 256 threads
    int b = blockIdx.x, ch = blockIdx.y;
    int t = threadIdx.x;
    int j = t & 63, ns = t >> 6;
    const float* base = g_logits + ((size_t)(b*NTOK + ch*512)) * JDIM + j;

    __shared__ float red[4][64];
    __shared__ float bm[64];

    float m = -1e30f;
    for (int i = ns; i < 512; i += 4) m = fmaxf(m, base[(size_t)i * JDIM]);
    red[ns][j] = m;
    __syncthreads();
    if (t < 64) bm[t] = fmaxf(fmaxf(red[0][t], red[1][t]), fmaxf(red[2][t], red[3][t]));
    __syncthreads();

    float mm = bm[j];
    float s = 0.f;
    for (int i = ns; i < 512; i += 4) s += __expf(base[(size_t)i * JDIM] - mm);
    __syncthreads();
    red[ns][j] = s;
    __syncthreads();
    if (t < 64) {
        g_pmax[(b*8 + ch)*JDIM + t] = bm[t];
        g_psum[(b*8 + ch)*JDIM + t] = red[0][t] + red[1][t] + red[2][t] + red[3][t];
    }
}

// ---------- K2b: combine 8 partials per (b, j); fold L1 norm (1+1e-9) ----------
__global__ void k_stats2() { // grid (16), 64 threads
    int b = blockIdx.x, j = threadIdx.x;
    float ms[8];
    float gm = -1e30f;
    #pragma unroll
    for (int ch = 0; ch < 8; ch++) {
        ms[ch] = g_pmax[(b*8 + ch)*JDIM + j];
        gm = fmaxf(gm, ms[ch]);
    }
    float Z = 0.f;
    #pragma unroll
    for (int ch = 0; ch < 8; ch++)
        Z += g_psum[(b*8 + ch)*JDIM + j] * __expf(ms[ch] - gm);
    g_rmax[b*JDIM + j] = gm;
    g_rinv[b*JDIM + j] = 1.f / (Z * (1.f + 1e-9f));
}

// ---------- K3: out = relu( BN( exp(logits-max)*inv @ M ) + inputs ) ----------
// grid (65536/128, 512/128). CTA tile 128x128, 8 warps: 4 m-strips x 2 n-halves.
__global__ __launch_bounds__(256) void k_out(const float* __restrict__ in,
                                             float* __restrict__ out) {
    __shared__ __align__(16) __nv_bfloat16 sM[128 * 72]; // [c_local][j], stride 72
    __shared__ float s_s[128], s_t[128], s_mx[64], s_iv[64];

    int tid = threadIdx.x;
    int mt = blockIdx.x, nt4 = blockIdx.y;
    int cbase = nt4 * 128;

    uint32_t* sm32 = reinterpret_cast<uint32_t*>(sM);
    const uint32_t* gm = reinterpret_cast<const uint32_t*>(g_Mbf) + cbase*32; // 32 words/row
    for (int i = tid; i < 128*32; i += 256) {
        int c = i >> 5, w = i & 31;
        sm32[c*36 + w] = gm[i];
    }
    if (tid < 128) { s_s[tid] = g_bns[cbase + tid]; s_t[tid] = g_bnt[cbase + tid]; }
    int b = mt >> 5; // 128-row tiles, 4096 rows/batch
    if (tid < 64) { s_mx[tid] = g_rmax[b*JDIM + tid]; s_iv[tid] = g_rinv[b*JDIM + tid]; }
    __syncthreads();

    int warp = tid >> 5, lane = tid & 31;
    int qr = lane >> 2, qc = lane & 3;
    int wm = warp & 3, wn = warp >> 2;
    int rowbase = mt*128 + wm*32;

    float acc[2][8][4];
    #pragma unroll
    for (int s = 0; s < 2; s++)
        #pragma unroll
        for (int nt = 0; nt < 8; nt++)
            #pragma unroll
            for (int r = 0; r < 4; r++) acc[s][nt][r] = 0.f;

    const float* lg = g_logits + (size_t)(rowbase + qr)*JDIM + qc*2;

    #pragma unroll
    for (int jj = 0; jj < 64; jj += 16) {
        int j0 = jj + qc*2;
        float mA = s_mx[j0],   mB = s_mx[j0+1], iA = s_iv[j0],   iB = s_iv[j0+1];
        float mC = s_mx[j0+8], mD = s_mx[j0+9], iC = s_iv[j0+8], iD = s_iv[j0+9];
        uint32_t a[2][4];
        #pragma unroll
        for (int s = 0; s < 2; s++) {
            const float* p = lg + s*16*JDIM + jj;
            float2 v0 = *reinterpret_cast<const float2*>(p);
            float2 v1 = *reinterpret_cast<const float2*>(p + 8*JDIM);
            float2 v2 = *reinterpret_cast<const float2*>(p + 8);
            float2 v3 = *reinterpret_cast<const float2*>(p + 8*JDIM + 8);
            a[s][0] = packbf(__expf(v0.x - mA)*iA, __expf(v0.y - mB)*iB);
            a[s][1] = packbf(__expf(v1.x - mA)*iA, __expf(v1.y - mB)*iB);
            a[s][2] = packbf(__expf(v2.x - mC)*iC, __expf(v2.y - mD)*iD);
            a[s][3] = packbf(__expf(v3.x - mC)*iC, __expf(v3.y - mD)*iD);
        }
        int bofs = (jj + qc*2) >> 1;
        #pragma unroll
        for (int nt = 0; nt < 8; nt++) {
            int cl = wn*64 + nt*8 + qr;
            uint32_t bb[2] = { sm32[cl*36 + bofs], sm32[cl*36 + bofs + 4] };
            mma16816(acc[0][nt], a[0], bb);
            mma16816(acc[1][nt], a[1], bb);
        }
    }

    #pragma unroll
    for (int s = 0; s < 2; s++)
        #pragma unroll
        for (int nt = 0; nt < 8; nt++) {
            int row = rowbase + s*16 + qr;
            int cl  = wn*64 + nt*8 + qc*2;
            int col = cbase + cl;
            float2 r0 = *reinterpret_cast<const float2*>(&in[(size_t)row*CDIM + col]);
            float2 r1 = *reinterpret_cast<const float2*>(&in[(size_t)(row + 8)*CDIM + col]);
            float2 o0, o1;
            o0.x = fmaxf(fmaf(acc[s][nt][0], s_s[cl],   s_t[cl])   + r0.x, 0.f);
            o0.y = fmaxf(fmaf(acc[s][nt][1], s_s[cl+1], s_t[cl+1]) + r0.y, 0.f);
            o1.x = fmaxf(fmaf(acc[s][nt][2], s_s[cl],   s_t[cl])   + r1.x, 0.f);
            o1.y = fmaxf(fmaf(acc[s][nt][3], s_s[cl+1], s_t[cl+1]) + r1.y, 0.f);
            *reinterpret_cast<float2*>(&out[(size_t)row*CDIM + col]) = o0;
            *reinterpret_cast<float2*>(&out[(size_t)(row + 8)*CDIM + col]) = o1;
        }
}

// ---------- launch ----------
extern "C" void kernel_launch(void* const* d_in, const int* in_sizes, int n_in,
                              void* d_out, int out_size) {
    (void)in_sizes; (void)n_in; (void)out_size;
    const float* inputs = (const float*)d_in[0];
    const float* w1     = (const float*)d_in[1];
    const float* b1     = (const float*)d_in[2];
    const float* m0     = (const float*)d_in[3];
    const float* m1     = (const float*)d_in[4];
    const float* w2     = (const float*)d_in[5];
    const float* gamma  = (const float*)d_in[6];
    const float* beta   = (const float*)d_in[7];
    const float* bmean  = (const float*)d_in[8];
    const float* bvar   = (const float*)d_in[9];

    k_fuse<<<(65536 + CDIM + JDIM + 255) / 256, 256>>>(w1, b1, m0, m1, w2,
                                                       gamma, beta, bmean, bvar);
    k_logits<<<ROWS / 256, 256>>>(inputs);
    k_stats1<<<dim3(BATCH, 8), 256>>>();
    k_stats2<<<BATCH, 64>>>();
    k_out<<<dim3(ROWS / 128, 4), 256>>>(inputs, (float*)d_out);
}